// round 15
// baseline (speedup 1.0000x reference)
#include <cuda_runtime.h>
#include <cuda_bf16.h>
#include <math.h>

#define BB   1024
#define TT   256
#define DH   128
#define G3   384
#define DX   64
#define DEPS 16
#define NB   152
#define GH_S 388
#define HB_S 136

__device__ __forceinline__ void mma16816(float* c, const unsigned* a, const unsigned* b) {
    asm volatile(
        "mma.sync.aligned.m16n8k16.row.col.f32.bf16.bf16.f32 "
        "{%0,%1,%2,%3}, {%4,%5,%6,%7}, {%8,%9}, {%0,%1,%2,%3};"
        : "+f"(c[0]), "+f"(c[1]), "+f"(c[2]), "+f"(c[3])
        : "r"(a[0]), "r"(a[1]), "r"(a[2]), "r"(a[3]), "r"(b[0]), "r"(b[1]));
}
__device__ __forceinline__ unsigned bfsplit_hi(float x, float y) {
    __nv_bfloat162 p; p.x = __float2bfloat16(x); p.y = __float2bfloat16(y);
    return *(unsigned*)&p;
}
__device__ __forceinline__ unsigned bfsplit_lo(float x, float y) {
    __nv_bfloat162 p;
    p.x = __float2bfloat16(x - __bfloat162float(__float2bfloat16(x)));
    p.y = __float2bfloat16(y - __bfloat162float(__float2bfloat16(y)));
    return *(unsigned*)&p;
}
__device__ __forceinline__ float fsigmoid(float x) {
    float e, r;
    asm("ex2.approx.f32 %0, %1;" : "=f"(e) : "f"(-1.4426950408889634f * x));
    asm("rcp.approx.f32 %0, %1;" : "=f"(r) : "f"(1.f + e));
    return r;
}
__device__ __forceinline__ float ftanh(float x) {
    float e, r;
    asm("ex2.approx.f32 %0, %1;" : "=f"(e) : "f"(-2.8853900817779268f * x));
    asm("rcp.approx.f32 %0, %1;" : "=f"(r) : "f"(1.f + e));
    return fmaf(2.f, r, -1.f);
}
__device__ __forceinline__ void cp4(unsigned dst, const void* src) {
    asm volatile("cp.async.ca.shared.global [%0], [%1], 4;" :: "r"(dst), "l"(src));
}

// 48-MMA split-bf16 recurrent GEMM, accumulators only (scatter deferred)
__device__ __forceinline__ void h_mma48(
    const __nv_bfloat16* hhi, const __nv_bfloat16* hlo,
    const unsigned Ahi[2][8][4], const unsigned Alo[2][8][4],
    float c[4][4], int grp, int q) {
    #pragma unroll
    for (int m = 0; m < 4; m++)
        #pragma unroll
        for (int i = 0; i < 4; i++) c[m][i] = 0.f;
    #pragma unroll
    for (int kc = 0; kc < 8; kc++) {
        int koff = kc * 16 + 2 * q;
        unsigned bh[2], bl[2];
        bh[0] = *(const unsigned*)&hhi[grp * HB_S + koff];
        bh[1] = *(const unsigned*)&hhi[grp * HB_S + koff + 8];
        bl[0] = *(const unsigned*)&hlo[grp * HB_S + koff];
        bl[1] = *(const unsigned*)&hlo[grp * HB_S + koff + 8];
        float* d0 = (kc & 1) ? c[1] : c[0];
        float* d1 = (kc & 1) ? c[3] : c[2];
        mma16816(d0, Ahi[0][kc], bh);
        mma16816(d1, Ahi[1][kc], bh);
        mma16816(d0, Alo[0][kc], bh);
        mma16816(d1, Alo[1][kc], bh);
        mma16816(d0, Ahi[0][kc], bl);
        mma16816(d1, Ahi[1][kc], bl);
    }
}
__device__ __forceinline__ void gh_scatter(float* Gh, const float c[4][4],
                                           int warp, int grp, int q) {
    int gsc = warp * 32 + grp;
    Gh[(2*q)   * GH_S + gsc]      = c[0][0] + c[1][0];
    Gh[(2*q+1) * GH_S + gsc]      = c[0][1] + c[1][1];
    Gh[(2*q)   * GH_S + gsc + 8]  = c[0][2] + c[1][2];
    Gh[(2*q+1) * GH_S + gsc + 8]  = c[0][3] + c[1][3];
    Gh[(2*q)   * GH_S + gsc + 16] = c[2][0] + c[3][0];
    Gh[(2*q+1) * GH_S + gsc + 16] = c[2][1] + c[3][1];
    Gh[(2*q)   * GH_S + gsc + 24] = c[2][2] + c[3][2];
    Gh[(2*q+1) * GH_S + gsc + 24] = c[2][3] + c[3][3];
}

// eps-MMA: sE[gate][row] = We . eps (split bf16)
__device__ __forceinline__ void eps_mma(
    const __nv_bfloat16* ehi, const __nv_bfloat16* elo,
    const unsigned* sWeAhi, const unsigned* sWeAlo,
    float* sE, int warp, int grp, int q) {
    unsigned bh[2], bl[2];
    bh[0] = *(const unsigned*)&ehi[grp * 20 + 2 * q];
    bh[1] = *(const unsigned*)&ehi[grp * 20 + 2 * q + 8];
    bl[0] = *(const unsigned*)&elo[grp * 20 + 2 * q];
    bl[1] = *(const unsigned*)&elo[grp * 20 + 2 * q + 8];
    float ce0[4] = {0,0,0,0}, ce1[4] = {0,0,0,0};
    #pragma unroll
    for (int mt = 0; mt < 2; mt++) {
        int gb = warp * 32 + mt * 16;
        unsigned ah[4], al[4];
        ah[0] = sWeAhi[(gb + grp) * 9 + q];
        ah[1] = sWeAhi[(gb + grp + 8) * 9 + q];
        ah[2] = sWeAhi[(gb + grp) * 9 + q + 4];
        ah[3] = sWeAhi[(gb + grp + 8) * 9 + q + 4];
        al[0] = sWeAlo[(gb + grp) * 9 + q];
        al[1] = sWeAlo[(gb + grp + 8) * 9 + q];
        al[2] = sWeAlo[(gb + grp) * 9 + q + 4];
        al[3] = sWeAlo[(gb + grp + 8) * 9 + q + 4];
        float* d = mt ? ce1 : ce0;
        mma16816(d, ah, bh);
        mma16816(d, ah, bl);
        mma16816(d, al, bh);
    }
    int gsc = warp * 32 + grp;
    sE[(2*q)   * GH_S + gsc]      = ce0[0];
    sE[(2*q+1) * GH_S + gsc]      = ce0[1];
    sE[(2*q)   * GH_S + gsc + 8]  = ce0[2];
    sE[(2*q+1) * GH_S + gsc + 8]  = ce0[3];
    sE[(2*q)   * GH_S + gsc + 16] = ce1[0];
    sE[(2*q+1) * GH_S + gsc + 16] = ce1[1];
    sE[(2*q)   * GH_S + gsc + 24] = ce1[2];
    sE[(2*q+1) * GH_S + gsc + 24] = ce1[3];
}

// group EW: ng rows at block-local base rloc
__device__ __forceinline__ void ew_group(
    int ng, int rloc, const float* Gh, const float* sga_t, const float* sEps_t,
    const float* sGxb, const float* sbhh, float* hsX,
    __nv_bfloat16* hhiX, __nv_bfloat16* hloX, int tid) {
    int lim = ng << 7;
    #pragma unroll
    for (int it = 0; it < 2; it++) {
        int i = tid + it * 384;
        if (i >= lim) break;
        int rl = i >> 7, j = i & 127;
        int rb = rloc + rl;
        const float* gab = sga_t + rb * 384;
        const float* gxb = sGxb + rb * 384;
        const float* se  = sEps_t + rb * GH_S;
        float gxr = gab[j]       + gxb[j]       + se[j];
        float gxz = gab[j + 128] + gxb[j + 128] + se[j + 128];
        float gxn = gab[j + 256] + gxb[j + 256] + se[j + 256];
        float ghr = Gh[rl * GH_S + j];
        float ghz = Gh[rl * GH_S + j + 128];
        float ghn = Gh[rl * GH_S + j + 256] + sbhh[j + 256];
        float rv = fsigmoid(gxr + ghr);
        float zv = fsigmoid(gxz + ghz);
        float nv = ftanh(gxn + rv * ghn);
        float hn = (1.f - zv) * nv + zv * hsX[i];
        hsX[i] = hn;
        __nv_bfloat16 hv = __float2bfloat16(hn);
        hhiX[rl * HB_S + j] = hv;
        hloX[rl * HB_S + j] = __float2bfloat16(hn - __bfloat162float(hv));
    }
}

__device__ __forceinline__ void epi_group(
    int ng, int rabs, int t, const float* hsX, const float* Wys, float by0,
    float* out, int warp, int lane) {
    if (warp < ng) {
        float s = 0.f;
        #pragma unroll
        for (int m = 0; m < 4; m++)
            s = fmaf(hsX[warp * 128 + lane + m * 32], Wys[lane + m * 32], s);
        s += __shfl_down_sync(0xffffffffu, s, 16);
        s += __shfl_down_sync(0xffffffffu, s, 8);
        s += __shfl_down_sync(0xffffffffu, s, 4);
        s += __shfl_down_sync(0xffffffffu, s, 2);
        s += __shfl_down_sync(0xffffffffu, s, 1);
        if (lane == 0) {
            float logit = s + by0;
            size_t o = ((size_t)(rabs + warp) * TT + t) * 2;
            out[o]     = logit;
            out[o + 1] = fsigmoid(logit);
        }
    }
}

// ---- scratch ----
__device__ float g_h0[BB * DH];
__device__ float g_Ga3[800 * G3];
__device__ float g_Gx[BB * G3];

// ============================================================================
// K_PRO (unchanged from R13)
// ============================================================================
__global__ void __launch_bounds__(384, 2)
k_pro(const float* __restrict__ x,  const float* __restrict__ Wx,
      const float* __restrict__ bx, const float* __restrict__ eps,
      const float* __restrict__ W0, const float* __restrict__ b0,
      const float* __restrict__ Ea, const float* __restrict__ Et,
      const float* __restrict__ Wih, const float* __restrict__ bih,
      const float* __restrict__ bhh) {
    __shared__ float s0[64], xe[64], e0[16];
    int bid = blockIdx.x, tid = threadIdx.x;

    if (bid < 1024) {
        int b = bid;
        if (tid < 64)              s0[tid]      = x[b * 64 + tid];
        if (tid >= 64 && tid < 80) e0[tid - 64] = eps[(size_t)b * TT * DEPS + (tid - 64)];
        __syncthreads();
        if (tid < 64) {
            float acc = bx[tid];
            #pragma unroll
            for (int k = 0; k < 64; k++) acc = fmaf(Wx[tid * 64 + k], s0[k], acc);
            xe[tid] = acc;
        }
        __syncthreads();
        if (tid < 128) {
            float acc = b0[tid];
            #pragma unroll
            for (int k = 0; k < 64; k++) acc = fmaf(W0[tid * 80 + k], xe[k], acc);
            #pragma unroll
            for (int k = 0; k < 16; k++) acc = fmaf(W0[tid * 80 + 64 + k], e0[k], acc);
            g_h0[b * DH + tid] = tanhf(acc);
        }
        {
            float acc = bih[tid] + ((tid < 256) ? bhh[tid] : 0.f);
            #pragma unroll
            for (int k = 0; k < 64; k++) acc = fmaf(Wih[tid * 129 + 48 + k], xe[k], acc);
            g_Gx[b * G3 + tid] = acc;
        }
    } else {
        int v = bid - 1024;
        int yb = v / 400;
        int rem = v - yb * 400;
        int tv = rem / 100;
        int av = rem - tv * 100;
        if (tid < 32)               s0[tid] = Ea[av * 32 + tid];
        if (tid >= 32 && tid < 48)  s0[tid] = Et[tv * 16 + (tid - 32)];
        __syncthreads();
        float acc = yb ? Wih[tid * 129 + 128] : 0.f;
        #pragma unroll
        for (int k = 0; k < 32; k++) acc = fmaf(Wih[tid * 129 + k], s0[k], acc);
        #pragma unroll
        for (int k = 0; k < 16; k++) acc = fmaf(Wih[tid * 129 + 32 + k], s0[32 + k], acc);
        g_Ga3[v * G3 + tid] = acc;
    }
}

// ============================================================================
// K_RNN: two-group software-pipelined GRU scan.
//  P1(t): MMA_A(t) || EW_B(t-1);  P2(t): MMA_B(t) || EW_A(t) || eps-MMA(t+1)
//  sga / sEps are 3-deep rings (t-1 reader vs t+1 writer parity).
// ============================================================================
#define NFLOAT (3104*2 + 3*3104 + 384 + 128 + 2688 + 3*2688 + 512 + 512)
#define SMB (NFLOAT * 4 + 6912 * 4 + (4 * 1088 + 2 * 320) * 2 + 1792 * 2 + 32)

__global__ void __launch_bounds__(384, 1)
k_rnn(const int* __restrict__ a, const int* __restrict__ tcat,
      const float* __restrict__ y, const float* __restrict__ eps,
      const float* __restrict__ Wih,
      const float* __restrict__ Whh, const float* __restrict__ bhh,
      const float* __restrict__ Wy,  const float* __restrict__ by,
      float* __restrict__ out) {
    extern __shared__ __align__(16) char smraw[];
    float* GhA  = (float*)smraw;          // 3104
    float* GhB  = GhA + 3104;             // 3104
    float* sEps = GhB + 3104;             // 3*3104
    float* sbhh = sEps + 3 * 3104;        // 384
    float* Wys  = sbhh + 384;             // 128
    float* sGxb = Wys + 128;              // 2688
    float* sga  = sGxb + 2688;            // 3*2688
    float* hsA  = sga + 3 * 2688;         // 512
    float* hsB  = hsA + 512;              // 512
    unsigned* sWeAhi = (unsigned*)(hsB + 512);   // 3456
    unsigned* sWeAlo = sWeAhi + 3456;            // 3456
    __nv_bfloat16* hhiA  = (__nv_bfloat16*)(sWeAlo + 3456);  // 1088
    __nv_bfloat16* hloA  = hhiA + 1088;
    __nv_bfloat16* hhiB  = hloA + 1088;
    __nv_bfloat16* hloB  = hhiB + 1088;
    __nv_bfloat16* epshi = hloB + 1088;   // 320
    __nv_bfloat16* epslo = epshi + 320;   // 320
    short* scode = (short*)(epslo + 320); // 1792

    int tid = threadIdx.x;
    int bid = blockIdx.x;
    int r0  = (bid * BB) / NB;
    int r1  = ((bid + 1) * BB) / NB;
    int nr  = r1 - r0;          // 6 or 7
    int nA  = nr - 3;           // 3 or 4
    const int nBg = 3;
    int nu  = nr * 128;
    int warp = tid >> 5, lane = tid & 31;
    int grp = lane >> 2, q = lane & 3;

    // Whh A-fragments (split bf16) resident in registers
    unsigned Ahi[2][8][4], Alo[2][8][4];
    #pragma unroll
    for (int mt = 0; mt < 2; mt++)
        #pragma unroll
        for (int kc = 0; kc < 8; kc++)
            #pragma unroll
            for (int i = 0; i < 4; i++) {
                int g = warp * 32 + mt * 16 + grp + ((i & 1) ? 8 : 0);
                int k = kc * 16 + 2 * q + ((i & 2) ? 8 : 0);
                float2 wv = *(const float2*)&Whh[g * 128 + k];
                Ahi[mt][kc][i] = bfsplit_hi(wv.x, wv.y);
                Alo[mt][kc][i] = bfsplit_lo(wv.x, wv.y);
            }

    // ---- prologue staging ----
    for (int i = tid; i < nr * 256; i += 384) {
        int r = i >> 8, s = i & 255;
        int av = a[(r0 + r) * TT + s];
        int tv = tcat[(r0 + r) * TT + s];
        int yb = (s == 0) ? 0 : (y[(r0 + r) * TT + s - 1] > 0.5f ? 1 : 0);
        scode[i] = (short)(av + 100 * tv + 400 * yb);
    }
    for (int i = tid; i < nr * G3; i += 384) sGxb[i] = g_Gx[r0 * G3 + i];
    {
        int g = tid;
        #pragma unroll
        for (int k2 = 0; k2 < 8; k2++) {
            float w0 = Wih[g * 129 + 112 + 2 * k2];
            float w1 = Wih[g * 129 + 112 + 2 * k2 + 1];
            sWeAhi[g * 9 + k2] = bfsplit_hi(w0, w1);
            sWeAlo[g * 9 + k2] = bfsplit_lo(w0, w1);
        }
    }
    // zero-pad h buffers
    for (int i = tid; i < 1088; i += 384) {
        hhiA[i] = __float2bfloat16(0.f); hloA[i] = hhiA[i];
        hhiB[i] = hhiA[i];               hloB[i] = hhiA[i];
    }
    for (int i = tid; i < 320; i += 384) { epshi[i] = __float2bfloat16(0.f); epslo[i] = epshi[i]; }
    __syncthreads();
    // h0 -> group buffers
    for (int i = tid; i < nu; i += 384) {
        float h = g_h0[r0 * DH + i];
        int r = i >> 7, j = i & 127;
        __nv_bfloat16 hv = __float2bfloat16(h);
        __nv_bfloat16 lv = __float2bfloat16(h - __bfloat162float(hv));
        if (r < nA) {
            hsA[r * 128 + j] = h;
            hhiA[r * HB_S + j] = hv; hloA[r * HB_S + j] = lv;
        } else {
            int rb = r - nA;
            hsB[rb * 128 + j] = h;
            hhiB[rb * HB_S + j] = hv; hloB[rb * HB_S + j] = lv;
        }
    }
    sbhh[tid] = bhh[tid];
    if (tid < 128) Wys[tid] = Wy[tid];
    float by0 = by[0];
    __syncthreads();

    // sga slot 0 (sync), epshi buf 0
    #pragma unroll
    for (int r = 0; r < 7; r++)
        if (r < nr) {
            int ca = scode[r * 256];
            sga[r * 384 + tid] = g_Ga3[ca * G3 + tid];
        }
    if (tid < 16 * nr) {
        int r = tid >> 4, k = tid & 15;
        float v = eps[((size_t)(r0 + r) * TT) * 16 + k];
        __nv_bfloat16 hv = __float2bfloat16(v);
        epshi[r * 20 + k] = hv;
        epslo[r * 20 + k] = __float2bfloat16(v - __bfloat162float(hv));
    }
    __syncthreads();
    eps_mma(epshi, epslo, sWeAhi, sWeAlo, sEps, warp, grp, q);
    __syncthreads();

    unsigned sga_addr = (unsigned)__cvta_generic_to_shared(sga);

    for (int t = 0; t < TT; t++) {
        int s3  = t % 3;
        int s3n = (t + 1) % 3;
        int s3p = (t + 2) % 3;       // == (t-1) mod 3
        int eb  = (t + 1) & 1;
        int tp1 = (t + 1) & 255;

        // ================= P1: MMA_A(t) || EW_B(t-1) =================
        if (t) epi_group(nA, r0, t - 1, hsA, Wys, by0, out, warp, lane);

        float epv = 0.f;
        if (tid < 16 * nr)
            epv = eps[((size_t)(r0 + (tid >> 4)) * TT + tp1) * 16 + (tid & 15)];
        #pragma unroll
        for (int r = 0; r < 7; r++)
            if (r < nr) {
                int ca = scode[r * 256 + tp1];
                cp4(sga_addr + (unsigned)(s3n * 2688 + r * 384 + tid) * 4,
                    &g_Ga3[ca * G3 + tid]);
            }
        asm volatile("cp.async.commit_group;");

        float cA[4][4];
        h_mma48(hhiA, hloA, Ahi, Alo, cA, grp, q);

        asm volatile("cp.async.wait_group 1;");
        if (tid < 16 * nr) {
            int r = tid >> 4, k = tid & 15;
            __nv_bfloat16 hv = __float2bfloat16(epv);
            epshi[eb * 160 + r * 20 + k] = hv;
            epslo[eb * 160 + r * 20 + k] = __float2bfloat16(epv - __bfloat162float(hv));
        }
        if (t)
            ew_group(nBg, nA, GhB, sga + s3p * 2688, sEps + s3p * 3104,
                     sGxb, sbhh, hsB, hhiB, hloB, tid);
        gh_scatter(GhA, cA, warp, grp, q);
        __syncthreads();

        // ================= P2: MMA_B(t) || EW_A(t) || eps-MMA(t+1) ====
        if (t) epi_group(nBg, r0 + nA, t - 1, hsB, Wys, by0, out, warp, lane);

        float cB[4][4];
        h_mma48(hhiB, hloB, Ahi, Alo, cB, grp, q);

        eps_mma(epshi + eb * 160, epslo + eb * 160,
                sWeAhi, sWeAlo, sEps + s3n * 3104, warp, grp, q);
        ew_group(nA, 0, GhA, sga + s3 * 2688, sEps + s3 * 3104,
                 sGxb, sbhh, hsA, hhiA, hloA, tid);
        gh_scatter(GhB, cB, warp, grp, q);
        __syncthreads();
    }

    // ---- drain: finish group A epilogue, group B EW+epilogue for t=255 ----
    {
        int sd = (TT - 1) % 3;   // 0
        epi_group(nA, r0, TT - 1, hsA, Wys, by0, out, warp, lane);
        ew_group(nBg, nA, GhB, sga + sd * 2688, sEps + sd * 3104,
                 sGxb, sbhh, hsB, hhiB, hloB, tid);
        __syncthreads();
        epi_group(nBg, r0 + nA, TT - 1, hsB, Wys, by0, out, warp, lane);
    }
    asm volatile("cp.async.wait_group 0;");
}

// ============================================================================
extern "C" void kernel_launch(void* const* d_in, const int* in_sizes, int n_in,
                              void* d_out, int out_size) {
    const float* x   = (const float*)d_in[0];
    const int*   a   = (const int*)  d_in[1];
    const int*   t   = (const int*)  d_in[2];
    const float* y   = (const float*)d_in[3];
    const float* eps = (const float*)d_in[5];
    const float* Wx  = (const float*)d_in[6];
    const float* bx  = (const float*)d_in[7];
    const float* Ea  = (const float*)d_in[8];
    const float* Et  = (const float*)d_in[9];
    const float* Wih = (const float*)d_in[10];
    const float* Whh = (const float*)d_in[11];
    const float* bih = (const float*)d_in[12];
    const float* bhh = (const float*)d_in[13];
    const float* W0  = (const float*)d_in[14];
    const float* b0  = (const float*)d_in[15];
    const float* Wy  = (const float*)d_in[16];
    const float* by  = (const float*)d_in[17];
    float* out = (float*)d_out;

    cudaFuncSetAttribute(k_rnn, cudaFuncAttributeMaxDynamicSharedMemorySize, SMB);

    k_pro<<<1824, 384>>>(x, Wx, bx, eps, W0, b0, Ea, Et, Wih, bih, bhh);
    k_rnn<<<NB, 384, SMB>>>(a, t, y, eps, Wih, Whh, bhh, Wy, by, out);
}

// round 16
// speedup vs baseline: 1.3216x; 1.3216x over previous
#include <cuda_runtime.h>
#include <cuda_bf16.h>
#include <math.h>

#define BB   1024
#define TT   256
#define DH   128
#define G3   384
#define DX   64
#define DEPS 16
#define NB   152
#define HB_S 136
#define SR   388     // [row][gate] stride for sga/sEps/sGxb (bank-clean: 388%32=4)

__device__ __forceinline__ void mma16816(float* c, const unsigned* a, const unsigned* b) {
    asm volatile(
        "mma.sync.aligned.m16n8k16.row.col.f32.bf16.bf16.f32 "
        "{%0,%1,%2,%3}, {%4,%5,%6,%7}, {%8,%9}, {%0,%1,%2,%3};"
        : "+f"(c[0]), "+f"(c[1]), "+f"(c[2]), "+f"(c[3])
        : "r"(a[0]), "r"(a[1]), "r"(a[2]), "r"(a[3]), "r"(b[0]), "r"(b[1]));
}
__device__ __forceinline__ unsigned bfsplit_hi(float x, float y) {
    __nv_bfloat162 p; p.x = __float2bfloat16(x); p.y = __float2bfloat16(y);
    return *(unsigned*)&p;
}
__device__ __forceinline__ unsigned bfsplit_lo(float x, float y) {
    __nv_bfloat162 p;
    p.x = __float2bfloat16(x - __bfloat162float(__float2bfloat16(x)));
    p.y = __float2bfloat16(y - __bfloat162float(__float2bfloat16(y)));
    return *(unsigned*)&p;
}
__device__ __forceinline__ float fsigmoid(float x) {
    float e, r;
    asm("ex2.approx.f32 %0, %1;" : "=f"(e) : "f"(-1.4426950408889634f * x));
    asm("rcp.approx.f32 %0, %1;" : "=f"(r) : "f"(1.f + e));
    return r;
}
__device__ __forceinline__ float ftanh(float x) {
    float e, r;
    asm("ex2.approx.f32 %0, %1;" : "=f"(e) : "f"(-2.8853900817779268f * x));
    asm("rcp.approx.f32 %0, %1;" : "=f"(r) : "f"(1.f + e));
    return fmaf(2.f, r, -1.f);
}
__device__ __forceinline__ void cp4(unsigned dst, const void* src) {
    asm volatile("cp.async.ca.shared.global [%0], [%1], 4;" :: "r"(dst), "l"(src));
}

// ---- scratch ----
__device__ float g_h0[BB * DH];
__device__ float g_Ga3[800 * G3];
__device__ float g_Gx[BB * G3];

// ============================================================================
// K_PRO (unchanged from R13)
// ============================================================================
__global__ void __launch_bounds__(384, 2)
k_pro(const float* __restrict__ x,  const float* __restrict__ Wx,
      const float* __restrict__ bx, const float* __restrict__ eps,
      const float* __restrict__ W0, const float* __restrict__ b0,
      const float* __restrict__ Ea, const float* __restrict__ Et,
      const float* __restrict__ Wih, const float* __restrict__ bih,
      const float* __restrict__ bhh) {
    __shared__ float s0[64], xe[64], e0[16];
    int bid = blockIdx.x, tid = threadIdx.x;

    if (bid < 1024) {
        int b = bid;
        if (tid < 64)              s0[tid]      = x[b * 64 + tid];
        if (tid >= 64 && tid < 80) e0[tid - 64] = eps[(size_t)b * TT * DEPS + (tid - 64)];
        __syncthreads();
        if (tid < 64) {
            float acc = bx[tid];
            #pragma unroll
            for (int k = 0; k < 64; k++) acc = fmaf(Wx[tid * 64 + k], s0[k], acc);
            xe[tid] = acc;
        }
        __syncthreads();
        if (tid < 128) {
            float acc = b0[tid];
            #pragma unroll
            for (int k = 0; k < 64; k++) acc = fmaf(W0[tid * 80 + k], xe[k], acc);
            #pragma unroll
            for (int k = 0; k < 16; k++) acc = fmaf(W0[tid * 80 + 64 + k], e0[k], acc);
            g_h0[b * DH + tid] = tanhf(acc);
        }
        {
            float acc = bih[tid] + ((tid < 256) ? bhh[tid] : 0.f);
            #pragma unroll
            for (int k = 0; k < 64; k++) acc = fmaf(Wih[tid * 129 + 48 + k], xe[k], acc);
            g_Gx[b * G3 + tid] = acc;
        }
    } else {
        int v = bid - 1024;
        int yb = v / 400;
        int rem = v - yb * 400;
        int tv = rem / 100;
        int av = rem - tv * 100;
        if (tid < 32)               s0[tid] = Ea[av * 32 + tid];
        if (tid >= 32 && tid < 48)  s0[tid] = Et[tv * 16 + (tid - 32)];
        __syncthreads();
        float acc = yb ? Wih[tid * 129 + 128] : 0.f;
        #pragma unroll
        for (int k = 0; k < 32; k++) acc = fmaf(Wih[tid * 129 + k], s0[k], acc);
        #pragma unroll
        for (int k = 0; k < 16; k++) acc = fmaf(Wih[tid * 129 + 32 + k], s0[32 + k], acc);
        g_Ga3[v * G3 + tid] = acc;
    }
}

// ============================================================================
// K_RNN: gate-aligned tiling. 256 threads = 8 warps; warp w owns units
// [16w,16w+16) and computes m-tiles for gates 16w (r), 128+16w (z), 256+16w (n).
// EW on MMA-output registers; h state in registers; ONE barrier per step.
// ============================================================================
// smem: floats[sga 2*3104 | sEps 2*3104 | sGxb 3104 | part 2*64]
//       u32[sWeAhi 3456 | sWeAlo 3456]
//       bf16[hhi 2*1088 | hlo 2*1088 | ehi 2*160 | elo 2*160]
//       short[scode 2048]
#define F_N   (6208 + 6208 + 3104 + 128)
#define SMB   (F_N * 4 + 6912 * 4 + 4992 * 2 + 4096 + 32)

__global__ void __launch_bounds__(256, 1)
k_rnn(const int* __restrict__ a, const int* __restrict__ tcat,
      const float* __restrict__ y, const float* __restrict__ eps,
      const float* __restrict__ Wih,
      const float* __restrict__ Whh, const float* __restrict__ bhh,
      const float* __restrict__ Wy,  const float* __restrict__ by,
      float* __restrict__ out) {
    extern __shared__ __align__(16) char smraw[];
    float* sga  = (float*)smraw;           // [2][8][SR]
    float* sEps = sga + 6208;              // [2][8][SR]
    float* sGxb = sEps + 6208;             // [8][SR]
    float* part = sGxb + 3104;             // [2][8 warps][8 rows]
    unsigned* sWeAhi = (unsigned*)(part + 128);   // [384][9]
    unsigned* sWeAlo = sWeAhi + 3456;
    __nv_bfloat16* hhi = (__nv_bfloat16*)(sWeAlo + 3456);  // [2][8][HB_S]
    __nv_bfloat16* hlo = hhi + 2176;
    __nv_bfloat16* ehi = hlo + 2176;       // [2][8][20]
    __nv_bfloat16* elo = ehi + 320;
    short* scode = (short*)(elo + 320);    // [8][256]

    int tid = threadIdx.x;
    int bid = blockIdx.x;
    int r0  = (bid * BB) / NB;
    int r1  = ((bid + 1) * BB) / NB;
    int nr  = r1 - r0;                     // 6 or 7
    int W = tid >> 5, lane = tid & 31;
    int grp = lane >> 2, q = lane & 3;
    int J0 = 16 * W;
    int j0 = J0 + grp, j1 = j0 + 8;
    int hr0 = 2 * q, hr1 = 2 * q + 1;

    // ---- Whh A-fragments (hi+lo, 3 tiles) in registers ----
    unsigned Ahi[3][8][4], Alo[3][8][4];
    #pragma unroll
    for (int tau = 0; tau < 3; tau++) {
        int gbase = tau * 128 + J0;
        #pragma unroll
        for (int kc = 0; kc < 8; kc++)
            #pragma unroll
            for (int i = 0; i < 4; i++) {
                int g = gbase + grp + ((i & 1) ? 8 : 0);
                int k = kc * 16 + 2 * q + ((i & 2) ? 8 : 0);
                float2 wv = *(const float2*)&Whh[g * 128 + k];
                Ahi[tau][kc][i] = bfsplit_hi(wv.x, wv.y);
                Alo[tau][kc][i] = bfsplit_lo(wv.x, wv.y);
            }
    }

    // ---- prologue staging ----
    for (int i = tid; i < nr * 256; i += 256) {
        int r = i >> 8, s = i & 255;
        int av = a[(r0 + r) * TT + s];
        int tv = tcat[(r0 + r) * TT + s];
        int yb = (s == 0) ? 0 : (y[(r0 + r) * TT + s - 1] > 0.5f ? 1 : 0);
        scode[i] = (short)(av + 100 * tv + 400 * yb);
    }
    for (int g = tid; g < G3; g += 256) {
        #pragma unroll
        for (int k2 = 0; k2 < 8; k2++) {
            float w0 = Wih[g * 129 + 112 + 2 * k2];
            float w1 = Wih[g * 129 + 112 + 2 * k2 + 1];
            sWeAhi[g * 9 + k2] = bfsplit_hi(w0, w1);
            sWeAlo[g * 9 + k2] = bfsplit_lo(w0, w1);
        }
    }
    for (int i = tid; i < 2176; i += 256) { hhi[i] = __float2bfloat16(0.f); hlo[i] = hhi[i]; }
    for (int i = tid; i < 320; i += 256)  { ehi[i] = __float2bfloat16(0.f); elo[i] = ehi[i]; }
    // sGxb [row][SR]
    #pragma unroll
    for (int it = 0; it < 12; it++) {
        int idx = it * 256 + tid;
        int r = idx / 384, g = idx - r * 384;
        if (r < nr) sGxb[r * SR + g] = g_Gx[(r0 + r) * G3 + g];
    }
    __syncthreads();

    // h state in registers: kk = {(j0,hr0),(j0,hr1),(j1,hr0),(j1,hr1)}
    float h[4] = {0.f, 0.f, 0.f, 0.f};
    if (hr0 < nr) { h[0] = g_h0[(r0 + hr0) * DH + j0]; h[2] = g_h0[(r0 + hr0) * DH + j1]; }
    if (hr1 < nr) { h[1] = g_h0[(r0 + hr1) * DH + j0]; h[3] = g_h0[(r0 + hr1) * DH + j1]; }
    // write h0 into hhi/hlo buf0
    {
        #pragma unroll
        for (int kk = 0; kk < 4; kk++) {
            int hr = (kk & 1) ? hr1 : hr0;
            int j  = (kk & 2) ? j1 : j0;
            __nv_bfloat16 hv = __float2bfloat16(h[kk]);
            hhi[hr * HB_S + j] = hv;
            hlo[hr * HB_S + j] = __float2bfloat16(h[kk] - __bfloat162float(hv));
        }
    }
    float bhn0 = bhh[256 + j0], bhn1 = bhh[256 + j1];
    float wy0 = Wy[j0], wy1 = Wy[j1];
    float by0 = by[0];

    // sga slot 0 (sync)
    #pragma unroll
    for (int it = 0; it < 12; it++) {
        int idx = it * 256 + tid;
        int r = idx / 384, g = idx - r * 384;
        if (r < nr) {
            int ca = scode[r * 256];
            sga[r * SR + g] = g_Ga3[ca * G3 + g];
        }
    }
    // eps(0) -> ehi buf0, eps(1) -> buf1
    if (tid < 128) {
        int r = tid >> 4, k = tid & 15;
        float v0 = 0.f, v1 = 0.f;
        if (r < nr) {
            v0 = eps[((size_t)(r0 + r) * TT) * 16 + k];
            v1 = eps[((size_t)(r0 + r) * TT + 1) * 16 + k];
        }
        __nv_bfloat16 p0 = __float2bfloat16(v0);
        ehi[r * 20 + k] = p0;
        elo[r * 20 + k] = __float2bfloat16(v0 - __bfloat162float(p0));
        __nv_bfloat16 p1 = __float2bfloat16(v1);
        ehi[160 + r * 20 + k] = p1;
        elo[160 + r * 20 + k] = __float2bfloat16(v1 - __bfloat162float(p1));
    }
    __syncthreads();

    // eps-MMA(0) -> sEps[0]
    {
        unsigned bh[2], bl[2];
        bh[0] = *(const unsigned*)&ehi[grp * 20 + 2 * q];
        bh[1] = *(const unsigned*)&ehi[grp * 20 + 2 * q + 8];
        bl[0] = *(const unsigned*)&elo[grp * 20 + 2 * q];
        bl[1] = *(const unsigned*)&elo[grp * 20 + 2 * q + 8];
        #pragma unroll
        for (int tau = 0; tau < 3; tau++) {
            int gb = tau * 128 + J0;
            unsigned ah[4], al[4];
            ah[0] = sWeAhi[(gb + grp) * 9 + q];
            ah[1] = sWeAhi[(gb + grp + 8) * 9 + q];
            ah[2] = sWeAhi[(gb + grp) * 9 + q + 4];
            ah[3] = sWeAhi[(gb + grp + 8) * 9 + q + 4];
            al[0] = sWeAlo[(gb + grp) * 9 + q];
            al[1] = sWeAlo[(gb + grp + 8) * 9 + q];
            al[2] = sWeAlo[(gb + grp) * 9 + q + 4];
            al[3] = sWeAlo[(gb + grp + 8) * 9 + q + 4];
            float ce[4] = {0.f, 0.f, 0.f, 0.f};
            mma16816(ce, ah, bh);
            mma16816(ce, ah, bl);
            mma16816(ce, al, bh);
            sEps[hr0 * SR + gb + grp]     = ce[0];
            sEps[hr1 * SR + gb + grp]     = ce[1];
            sEps[hr0 * SR + gb + grp + 8] = ce[2];
            sEps[hr1 * SR + gb + grp + 8] = ce[3];
        }
    }
    __syncthreads();

    unsigned sga_sa = (unsigned)__cvta_generic_to_shared(sga);

    for (int t = 0; t < TT; t++) {
        int buf = t & 1, nbuf = buf ^ 1;
        int tp1 = (t + 1) & 255;
        int tp2 = (t + 2) & 255;

        // ---- LDG eps(t+2) ----
        float epv = 0.f;
        if (tid < 128 && (tid >> 4) < nr)
            epv = eps[((size_t)(r0 + (tid >> 4)) * TT + tp2) * 16 + (tid & 15)];

        // ---- cp.async sga slot (t+1)&1 ----
        #pragma unroll
        for (int it = 0; it < 12; it++) {
            int idx = it * 256 + tid;
            int r = idx / 384, g = idx - r * 384;
            if (r < nr) {
                int ca = scode[r * 256 + tp1];
                cp4(sga_sa + (unsigned)(nbuf * 3104 + r * SR + g) * 4,
                    &g_Ga3[ca * G3 + g]);
            }
        }
        asm volatile("cp.async.commit_group;");

        // ---- h-MMA: 3 tiles x 8 kc x 3 products ----
        float c[3][2][4];
        #pragma unroll
        for (int tau = 0; tau < 3; tau++)
            #pragma unroll
            for (int e = 0; e < 2; e++)
                #pragma unroll
                for (int i = 0; i < 4; i++) c[tau][e][i] = 0.f;
        {
            const __nv_bfloat16* hb = hhi + buf * 1088;
            const __nv_bfloat16* lb = hlo + buf * 1088;
            #pragma unroll
            for (int kc = 0; kc < 8; kc++) {
                int koff = kc * 16 + 2 * q;
                unsigned bh[2], bl[2];
                bh[0] = *(const unsigned*)&hb[grp * HB_S + koff];
                bh[1] = *(const unsigned*)&hb[grp * HB_S + koff + 8];
                bl[0] = *(const unsigned*)&lb[grp * HB_S + koff];
                bl[1] = *(const unsigned*)&lb[grp * HB_S + koff + 8];
                #pragma unroll
                for (int tau = 0; tau < 3; tau++) {
                    float* d = c[tau][kc & 1];
                    mma16816(d, Ahi[tau][kc], bh);
                    mma16816(d, Alo[tau][kc], bh);
                    mma16816(d, Ahi[tau][kc], bl);
                }
            }
        }

        // ---- eps-MMA(t+1) -> sEps[nbuf] (from ehi[(t+1)&1]) ----
        {
            const __nv_bfloat16* eh = ehi + nbuf * 160;
            const __nv_bfloat16* el = elo + nbuf * 160;
            unsigned bh[2], bl[2];
            bh[0] = *(const unsigned*)&eh[grp * 20 + 2 * q];
            bh[1] = *(const unsigned*)&eh[grp * 20 + 2 * q + 8];
            bl[0] = *(const unsigned*)&el[grp * 20 + 2 * q];
            bl[1] = *(const unsigned*)&el[grp * 20 + 2 * q + 8];
            float* sE = sEps + nbuf * 3104;
            #pragma unroll
            for (int tau = 0; tau < 3; tau++) {
                int gb = tau * 128 + J0;
                unsigned ah[4], al[4];
                ah[0] = sWeAhi[(gb + grp) * 9 + q];
                ah[1] = sWeAhi[(gb + grp + 8) * 9 + q];
                ah[2] = sWeAhi[(gb + grp) * 9 + q + 4];
                ah[3] = sWeAhi[(gb + grp + 8) * 9 + q + 4];
                al[0] = sWeAlo[(gb + grp) * 9 + q];
                al[1] = sWeAlo[(gb + grp + 8) * 9 + q];
                al[2] = sWeAlo[(gb + grp) * 9 + q + 4];
                al[3] = sWeAlo[(gb + grp + 8) * 9 + q + 4];
                float ce[4] = {0.f, 0.f, 0.f, 0.f};
                mma16816(ce, ah, bh);
                mma16816(ce, ah, bl);
                mma16816(ce, al, bh);
                sE[hr0 * SR + gb + grp]     = ce[0];
                sE[hr1 * SR + gb + grp]     = ce[1];
                sE[hr0 * SR + gb + grp + 8] = ce[2];
                sE[hr1 * SR + gb + grp + 8] = ce[3];
            }
        }

        // ---- EW on registers ----
        {
            const float* ga = sga + buf * 3104;
            const float* se = sEps + buf * 3104;
            float p0 = 0.f, p1 = 0.f;
            #pragma unroll
            for (int kk = 0; kk < 4; kk++) {
                int hr = (kk & 1) ? hr1 : hr0;
                int j  = (kk & 2) ? j1 : j0;
                float ghr = c[0][0][kk] + c[0][1][kk];
                float ghz = c[1][0][kk] + c[1][1][kk];
                float ghn = c[2][0][kk] + c[2][1][kk] + ((kk & 2) ? bhn1 : bhn0);
                int base = hr * SR + j;
                float gxr = ga[base]       + sGxb[base]       + se[base];
                float gxz = ga[base + 128] + sGxb[base + 128] + se[base + 128];
                float gxn = ga[base + 256] + sGxb[base + 256] + se[base + 256];
                float rv = fsigmoid(gxr + ghr);
                float zv = fsigmoid(gxz + ghz);
                float nv = ftanh(gxn + rv * ghn);
                float hn = (1.f - zv) * nv + zv * h[kk];
                h[kk] = hn;
                __nv_bfloat16 hv = __float2bfloat16(hn);
                hhi[nbuf * 1088 + hr * HB_S + j] = hv;
                hlo[nbuf * 1088 + hr * HB_S + j] = __float2bfloat16(hn - __bfloat162float(hv));
                float contrib = hn * ((kk & 2) ? wy1 : wy0);
                if (kk & 1) p1 += contrib; else p0 += contrib;
            }
            // reduce over grp (lanes stride 4)
            p0 += __shfl_down_sync(0xffffffffu, p0, 16);
            p1 += __shfl_down_sync(0xffffffffu, p1, 16);
            p0 += __shfl_down_sync(0xffffffffu, p0, 8);
            p1 += __shfl_down_sync(0xffffffffu, p1, 8);
            p0 += __shfl_down_sync(0xffffffffu, p0, 4);
            p1 += __shfl_down_sync(0xffffffffu, p1, 4);
            if (grp == 0) {
                part[buf * 64 + W * 8 + hr0] = p0;
                part[buf * 64 + W * 8 + hr1] = p1;
            }
        }

        // ---- stage eps(t+2) -> ehi[(t+2)&1 == buf] ----
        if (tid < 128) {
            int r = tid >> 4, k = tid & 15;
            __nv_bfloat16 pv = __float2bfloat16(epv);
            ehi[buf * 160 + r * 20 + k] = pv;
            elo[buf * 160 + r * 20 + k] = __float2bfloat16(epv - __bfloat162float(pv));
        }

        asm volatile("cp.async.wait_group 0;");
        __syncthreads();

        // ---- epilogue: logits(t) from partials (warp 0) ----
        if (tid < 8 && tid < nr) {
            float s = 0.f;
            #pragma unroll
            for (int w = 0; w < 8; w++) s += part[buf * 64 + w * 8 + tid];
            float logit = s + by0;
            size_t o = ((size_t)(r0 + tid) * TT + t) * 2;
            out[o]     = logit;
            out[o + 1] = fsigmoid(logit);
        }
    }
}

// ============================================================================
extern "C" void kernel_launch(void* const* d_in, const int* in_sizes, int n_in,
                              void* d_out, int out_size) {
    const float* x   = (const float*)d_in[0];
    const int*   a   = (const int*)  d_in[1];
    const int*   t   = (const int*)  d_in[2];
    const float* y   = (const float*)d_in[3];
    const float* eps = (const float*)d_in[5];
    const float* Wx  = (const float*)d_in[6];
    const float* bx  = (const float*)d_in[7];
    const float* Ea  = (const float*)d_in[8];
    const float* Et  = (const float*)d_in[9];
    const float* Wih = (const float*)d_in[10];
    const float* Whh = (const float*)d_in[11];
    const float* bih = (const float*)d_in[12];
    const float* bhh = (const float*)d_in[13];
    const float* W0  = (const float*)d_in[14];
    const float* b0  = (const float*)d_in[15];
    const float* Wy  = (const float*)d_in[16];
    const float* by  = (const float*)d_in[17];
    float* out = (float*)d_out;

    cudaFuncSetAttribute(k_rnn, cudaFuncAttributeMaxDynamicSharedMemorySize, SMB);

    k_pro<<<1824, 384>>>(x, Wx, bx, eps, W0, b0, Ea, Et, Wih, bih, bhh);
    k_rnn<<<NB, 256, SMB>>>(a, t, y, eps, Wih, Whh, bhh, Wy, by, out);
}

// round 17
// speedup vs baseline: 1.3264x; 1.0037x over previous
#include <cuda_runtime.h>
#include <cuda_bf16.h>
#include <math.h>

#define BB   1024
#define TT   256
#define DH   128
#define G3   384
#define DX   64
#define DEPS 16
#define NB   152
#define HB_S 136
#define SR   388

__device__ __forceinline__ void mma16816(float* c, const unsigned* a, const unsigned* b) {
    asm volatile(
        "mma.sync.aligned.m16n8k16.row.col.f32.bf16.bf16.f32 "
        "{%0,%1,%2,%3}, {%4,%5,%6,%7}, {%8,%9}, {%0,%1,%2,%3};"
        : "+f"(c[0]), "+f"(c[1]), "+f"(c[2]), "+f"(c[3])
        : "r"(a[0]), "r"(a[1]), "r"(a[2]), "r"(a[3]), "r"(b[0]), "r"(b[1]));
}
__device__ __forceinline__ void ldsm4(unsigned* r, unsigned addr) {
    asm volatile(
        "ldmatrix.sync.aligned.m8n8.x4.shared.b16 {%0,%1,%2,%3}, [%4];"
        : "=r"(r[0]), "=r"(r[1]), "=r"(r[2]), "=r"(r[3]) : "r"(addr));
}
__device__ __forceinline__ unsigned bfsplit_hi(float x, float y) {
    __nv_bfloat162 p; p.x = __float2bfloat16(x); p.y = __float2bfloat16(y);
    return *(unsigned*)&p;
}
__device__ __forceinline__ unsigned bfsplit_lo(float x, float y) {
    __nv_bfloat162 p;
    p.x = __float2bfloat16(x - __bfloat162float(__float2bfloat16(x)));
    p.y = __float2bfloat16(y - __bfloat162float(__float2bfloat16(y)));
    return *(unsigned*)&p;
}
__device__ __forceinline__ float fsigmoid(float x) {
    float e, r;
    asm("ex2.approx.f32 %0, %1;" : "=f"(e) : "f"(-1.4426950408889634f * x));
    asm("rcp.approx.f32 %0, %1;" : "=f"(r) : "f"(1.f + e));
    return r;
}
__device__ __forceinline__ float ftanh(float x) {
    float e, r;
    asm("ex2.approx.f32 %0, %1;" : "=f"(e) : "f"(-2.8853900817779268f * x));
    asm("rcp.approx.f32 %0, %1;" : "=f"(r) : "f"(1.f + e));
    return fmaf(2.f, r, -1.f);
}
__device__ __forceinline__ void cp4(unsigned dst, const void* src) {
    asm volatile("cp.async.ca.shared.global [%0], [%1], 4;" :: "r"(dst), "l"(src));
}

// ---- scratch ----
__device__ float g_h0[BB * DH];
__device__ float g_Ga3[800 * G3];
__device__ float g_Gx[BB * G3];

// ============================================================================
// K_PRO (unchanged from R13)
// ============================================================================
__global__ void __launch_bounds__(384, 2)
k_pro(const float* __restrict__ x,  const float* __restrict__ Wx,
      const float* __restrict__ bx, const float* __restrict__ eps,
      const float* __restrict__ W0, const float* __restrict__ b0,
      const float* __restrict__ Ea, const float* __restrict__ Et,
      const float* __restrict__ Wih, const float* __restrict__ bih,
      const float* __restrict__ bhh) {
    __shared__ float s0[64], xe[64], e0[16];
    int bid = blockIdx.x, tid = threadIdx.x;

    if (bid < 1024) {
        int b = bid;
        if (tid < 64)              s0[tid]      = x[b * 64 + tid];
        if (tid >= 64 && tid < 80) e0[tid - 64] = eps[(size_t)b * TT * DEPS + (tid - 64)];
        __syncthreads();
        if (tid < 64) {
            float acc = bx[tid];
            #pragma unroll
            for (int k = 0; k < 64; k++) acc = fmaf(Wx[tid * 64 + k], s0[k], acc);
            xe[tid] = acc;
        }
        __syncthreads();
        if (tid < 128) {
            float acc = b0[tid];
            #pragma unroll
            for (int k = 0; k < 64; k++) acc = fmaf(W0[tid * 80 + k], xe[k], acc);
            #pragma unroll
            for (int k = 0; k < 16; k++) acc = fmaf(W0[tid * 80 + 64 + k], e0[k], acc);
            g_h0[b * DH + tid] = tanhf(acc);
        }
        {
            float acc = bih[tid] + ((tid < 256) ? bhh[tid] : 0.f);
            #pragma unroll
            for (int k = 0; k < 64; k++) acc = fmaf(Wih[tid * 129 + 48 + k], xe[k], acc);
            g_Gx[b * G3 + tid] = acc;
        }
    } else {
        int v = bid - 1024;
        int yb = v / 400;
        int rem = v - yb * 400;
        int tv = rem / 100;
        int av = rem - tv * 100;
        if (tid < 32)               s0[tid] = Ea[av * 32 + tid];
        if (tid >= 32 && tid < 48)  s0[tid] = Et[tv * 16 + (tid - 32)];
        __syncthreads();
        float acc = yb ? Wih[tid * 129 + 128] : 0.f;
        #pragma unroll
        for (int k = 0; k < 32; k++) acc = fmaf(Wih[tid * 129 + k], s0[k], acc);
        #pragma unroll
        for (int k = 0; k < 16; k++) acc = fmaf(Wih[tid * 129 + 32 + k], s0[32 + k], acc);
        g_Ga3[v * G3 + tid] = acc;
    }
}

// ============================================================================
// K_RNN: gate-aligned tiling (R16) with Whh-lo fragments in SMEM via ldmatrix
// (kills register spills). 256 threads; ONE barrier per step.
// ============================================================================
#define F_N   (6208 + 6208 + 3104 + 128)
#define WLO_N (384 * 136)
#define SMB   (F_N * 4 + 6912 * 4 + (WLO_N + 2 * 2176 + 2 * 320) * 2 + 4096 + 32)

__global__ void __launch_bounds__(256, 1)
k_rnn(const int* __restrict__ a, const int* __restrict__ tcat,
      const float* __restrict__ y, const float* __restrict__ eps,
      const float* __restrict__ Wih,
      const float* __restrict__ Whh, const float* __restrict__ bhh,
      const float* __restrict__ Wy,  const float* __restrict__ by,
      float* __restrict__ out) {
    extern __shared__ __align__(16) char smraw[];
    float* sga  = (float*)smraw;           // [2][8][SR]
    float* sEps = sga + 6208;              // [2][8][SR]
    float* sGxb = sEps + 6208;             // [8][SR]
    float* part = sGxb + 3104;             // [2][8][8]
    unsigned* sWeAhi = (unsigned*)(part + 128);   // [384][9]
    unsigned* sWeAlo = sWeAhi + 3456;
    __nv_bfloat16* sWlo = (__nv_bfloat16*)(sWeAlo + 3456);  // [384][136]
    __nv_bfloat16* hhi = sWlo + WLO_N;     // [2][8][HB_S]
    __nv_bfloat16* hlo = hhi + 2176;
    __nv_bfloat16* ehi = hlo + 2176;       // [2][8][20]
    __nv_bfloat16* elo = ehi + 320;
    short* scode = (short*)(elo + 320);    // [8][256]

    int tid = threadIdx.x;
    int bid = blockIdx.x;
    int r0  = (bid * BB) / NB;
    int r1  = ((bid + 1) * BB) / NB;
    int nr  = r1 - r0;                     // 6 or 7
    int W = tid >> 5, lane = tid & 31;
    int grp = lane >> 2, q = lane & 3;
    int J0 = 16 * W;
    int j0 = J0 + grp, j1 = j0 + 8;
    int hr0 = 2 * q, hr1 = 2 * q + 1;

    // ---- Whh hi-fragments (3 tiles) in registers ----
    unsigned Ahi[3][8][4];
    #pragma unroll
    for (int tau = 0; tau < 3; tau++) {
        int gbase = tau * 128 + J0;
        #pragma unroll
        for (int kc = 0; kc < 8; kc++)
            #pragma unroll
            for (int i = 0; i < 4; i++) {
                int g = gbase + grp + ((i & 1) ? 8 : 0);
                int k = kc * 16 + 2 * q + ((i & 2) ? 8 : 0);
                float2 wv = *(const float2*)&Whh[g * 128 + k];
                Ahi[tau][kc][i] = bfsplit_hi(wv.x, wv.y);
            }
    }

    // ---- ldmatrix lane base for lo-fragments ----
    int mat = lane >> 3, r8 = lane & 7;
    int lrow0 = J0 + ((mat & 1) << 3) + r8;     // row within warp's 16-row tile
    int lcol0 = (mat >> 1) << 3;
    unsigned wloA = (unsigned)__cvta_generic_to_shared(sWlo);
    unsigned lm_base = wloA + (unsigned)((lrow0 * 136 + lcol0) * 2);
    // addr(tau,kc) = lm_base + tau*128*272 + kc*32

    // ---- prologue staging ----
    for (int i = tid; i < nr * 256; i += 256) {
        int r = i >> 8, s = i & 255;
        int av = a[(r0 + r) * TT + s];
        int tv = tcat[(r0 + r) * TT + s];
        int yb = (s == 0) ? 0 : (y[(r0 + r) * TT + s - 1] > 0.5f ? 1 : 0);
        scode[i] = (short)(av + 100 * tv + 400 * yb);
    }
    // Whh-lo -> smem (pairs)
    for (int idx = tid; idx < 384 * 64; idx += 256) {
        int g = idx >> 6, kp = idx & 63;
        float2 wv = *(const float2*)&Whh[g * 128 + 2 * kp];
        *(unsigned*)&sWlo[g * 136 + 2 * kp] = bfsplit_lo(wv.x, wv.y);
    }
    for (int g = tid; g < G3; g += 256) {
        #pragma unroll
        for (int k2 = 0; k2 < 8; k2++) {
            float w0 = Wih[g * 129 + 112 + 2 * k2];
            float w1 = Wih[g * 129 + 112 + 2 * k2 + 1];
            sWeAhi[g * 9 + k2] = bfsplit_hi(w0, w1);
            sWeAlo[g * 9 + k2] = bfsplit_lo(w0, w1);
        }
    }
    for (int i = tid; i < 2176; i += 256) { hhi[i] = __float2bfloat16(0.f); hlo[i] = hhi[i]; }
    for (int i = tid; i < 320; i += 256)  { ehi[i] = __float2bfloat16(0.f); elo[i] = ehi[i]; }
    #pragma unroll
    for (int it = 0; it < 12; it++) {
        int idx = it * 256 + tid;
        int r = idx / 384, g = idx - r * 384;
        if (r < nr) sGxb[r * SR + g] = g_Gx[(r0 + r) * G3 + g];
    }
    __syncthreads();

    // h state in registers
    float h[4] = {0.f, 0.f, 0.f, 0.f};
    if (hr0 < nr) { h[0] = g_h0[(r0 + hr0) * DH + j0]; h[2] = g_h0[(r0 + hr0) * DH + j1]; }
    if (hr1 < nr) { h[1] = g_h0[(r0 + hr1) * DH + j0]; h[3] = g_h0[(r0 + hr1) * DH + j1]; }
    {
        #pragma unroll
        for (int kk = 0; kk < 4; kk++) {
            int hr = (kk & 1) ? hr1 : hr0;
            int j  = (kk & 2) ? j1 : j0;
            __nv_bfloat16 hv = __float2bfloat16(h[kk]);
            hhi[hr * HB_S + j] = hv;
            hlo[hr * HB_S + j] = __float2bfloat16(h[kk] - __bfloat162float(hv));
        }
    }
    float bhn0 = bhh[256 + j0], bhn1 = bhh[256 + j1];
    float wy0 = Wy[j0], wy1 = Wy[j1];
    float by0 = by[0];

    // sga slot 0 (sync)
    #pragma unroll
    for (int it = 0; it < 12; it++) {
        int idx = it * 256 + tid;
        int r = idx / 384, g = idx - r * 384;
        if (r < nr) {
            int ca = scode[r * 256];
            sga[r * SR + g] = g_Ga3[ca * G3 + g];
        }
    }
    if (tid < 128) {
        int r = tid >> 4, k = tid & 15;
        float v0 = 0.f, v1 = 0.f;
        if (r < nr) {
            v0 = eps[((size_t)(r0 + r) * TT) * 16 + k];
            v1 = eps[((size_t)(r0 + r) * TT + 1) * 16 + k];
        }
        __nv_bfloat16 p0 = __float2bfloat16(v0);
        ehi[r * 20 + k] = p0;
        elo[r * 20 + k] = __float2bfloat16(v0 - __bfloat162float(p0));
        __nv_bfloat16 p1 = __float2bfloat16(v1);
        ehi[160 + r * 20 + k] = p1;
        elo[160 + r * 20 + k] = __float2bfloat16(v1 - __bfloat162float(p1));
    }
    __syncthreads();

    // eps-MMA(0) -> sEps[0]
    {
        unsigned bh[2], bl[2];
        bh[0] = *(const unsigned*)&ehi[grp * 20 + 2 * q];
        bh[1] = *(const unsigned*)&ehi[grp * 20 + 2 * q + 8];
        bl[0] = *(const unsigned*)&elo[grp * 20 + 2 * q];
        bl[1] = *(const unsigned*)&elo[grp * 20 + 2 * q + 8];
        #pragma unroll
        for (int tau = 0; tau < 3; tau++) {
            int gb = tau * 128 + J0;
            unsigned ah[4], al[4];
            ah[0] = sWeAhi[(gb + grp) * 9 + q];
            ah[1] = sWeAhi[(gb + grp + 8) * 9 + q];
            ah[2] = sWeAhi[(gb + grp) * 9 + q + 4];
            ah[3] = sWeAhi[(gb + grp + 8) * 9 + q + 4];
            al[0] = sWeAlo[(gb + grp) * 9 + q];
            al[1] = sWeAlo[(gb + grp + 8) * 9 + q];
            al[2] = sWeAlo[(gb + grp) * 9 + q + 4];
            al[3] = sWeAlo[(gb + grp + 8) * 9 + q + 4];
            float ce[4] = {0.f, 0.f, 0.f, 0.f};
            mma16816(ce, ah, bh);
            mma16816(ce, ah, bl);
            mma16816(ce, al, bh);
            sEps[hr0 * SR + gb + grp]     = ce[0];
            sEps[hr1 * SR + gb + grp]     = ce[1];
            sEps[hr0 * SR + gb + grp + 8] = ce[2];
            sEps[hr1 * SR + gb + grp + 8] = ce[3];
        }
    }
    __syncthreads();

    unsigned sga_sa = (unsigned)__cvta_generic_to_shared(sga);

    for (int t = 0; t < TT; t++) {
        int buf = t & 1, nbuf = buf ^ 1;
        int tp1 = (t + 1) & 255;
        int tp2 = (t + 2) & 255;

        // ---- LDG eps(t+2) ----
        float epv = 0.f;
        if (tid < 128 && (tid >> 4) < nr)
            epv = eps[((size_t)(r0 + (tid >> 4)) * TT + tp2) * 16 + (tid & 15)];

        // ---- cp.async sga slot (t+1)&1 ----
        #pragma unroll
        for (int it = 0; it < 12; it++) {
            int idx = it * 256 + tid;
            int r = idx / 384, g = idx - r * 384;
            if (r < nr) {
                int ca = scode[r * 256 + tp1];
                cp4(sga_sa + (unsigned)(nbuf * 3104 + r * SR + g) * 4,
                    &g_Ga3[ca * G3 + g]);
            }
        }
        asm volatile("cp.async.commit_group;");

        // ---- h-MMA: hi from regs, lo via ldmatrix ----
        float c[3][2][4];
        #pragma unroll
        for (int tau = 0; tau < 3; tau++)
            #pragma unroll
            for (int e = 0; e < 2; e++)
                #pragma unroll
                for (int i = 0; i < 4; i++) c[tau][e][i] = 0.f;
        {
            const __nv_bfloat16* hb = hhi + buf * 1088;
            const __nv_bfloat16* lb = hlo + buf * 1088;
            #pragma unroll
            for (int kc = 0; kc < 8; kc++) {
                int koff = kc * 16 + 2 * q;
                unsigned bh[2], bl[2];
                bh[0] = *(const unsigned*)&hb[grp * HB_S + koff];
                bh[1] = *(const unsigned*)&hb[grp * HB_S + koff + 8];
                bl[0] = *(const unsigned*)&lb[grp * HB_S + koff];
                bl[1] = *(const unsigned*)&lb[grp * HB_S + koff + 8];
                #pragma unroll
                for (int tau = 0; tau < 3; tau++) {
                    float* d = c[tau][kc & 1];
                    unsigned alo[4];
                    ldsm4(alo, lm_base + (unsigned)(tau * 34816 + kc * 32));
                    mma16816(d, Ahi[tau][kc], bh);
                    mma16816(d, alo, bh);
                    mma16816(d, Ahi[tau][kc], bl);
                }
            }
        }

        // ---- eps-MMA(t+1) -> sEps[nbuf] ----
        {
            const __nv_bfloat16* eh = ehi + nbuf * 160;
            const __nv_bfloat16* el = elo + nbuf * 160;
            unsigned bh[2], bl[2];
            bh[0] = *(const unsigned*)&eh[grp * 20 + 2 * q];
            bh[1] = *(const unsigned*)&eh[grp * 20 + 2 * q + 8];
            bl[0] = *(const unsigned*)&el[grp * 20 + 2 * q];
            bl[1] = *(const unsigned*)&el[grp * 20 + 2 * q + 8];
            float* sE = sEps + nbuf * 3104;
            #pragma unroll
            for (int tau = 0; tau < 3; tau++) {
                int gb = tau * 128 + J0;
                unsigned ah[4], al[4];
                ah[0] = sWeAhi[(gb + grp) * 9 + q];
                ah[1] = sWeAhi[(gb + grp + 8) * 9 + q];
                ah[2] = sWeAhi[(gb + grp) * 9 + q + 4];
                ah[3] = sWeAhi[(gb + grp + 8) * 9 + q + 4];
                al[0] = sWeAlo[(gb + grp) * 9 + q];
                al[1] = sWeAlo[(gb + grp + 8) * 9 + q];
                al[2] = sWeAlo[(gb + grp) * 9 + q + 4];
                al[3] = sWeAlo[(gb + grp + 8) * 9 + q + 4];
                float ce[4] = {0.f, 0.f, 0.f, 0.f};
                mma16816(ce, ah, bh);
                mma16816(ce, ah, bl);
                mma16816(ce, al, bh);
                sE[hr0 * SR + gb + grp]     = ce[0];
                sE[hr1 * SR + gb + grp]     = ce[1];
                sE[hr0 * SR + gb + grp + 8] = ce[2];
                sE[hr1 * SR + gb + grp + 8] = ce[3];
            }
        }

        // ---- EW on registers ----
        {
            const float* ga = sga + buf * 3104;
            const float* se = sEps + buf * 3104;
            float p0 = 0.f, p1 = 0.f;
            #pragma unroll
            for (int kk = 0; kk < 4; kk++) {
                int hr = (kk & 1) ? hr1 : hr0;
                int j  = (kk & 2) ? j1 : j0;
                float ghr = c[0][0][kk] + c[0][1][kk];
                float ghz = c[1][0][kk] + c[1][1][kk];
                float ghn = c[2][0][kk] + c[2][1][kk] + ((kk & 2) ? bhn1 : bhn0);
                int base = hr * SR + j;
                float gxr = ga[base]       + sGxb[base]       + se[base];
                float gxz = ga[base + 128] + sGxb[base + 128] + se[base + 128];
                float gxn = ga[base + 256] + sGxb[base + 256] + se[base + 256];
                float rv = fsigmoid(gxr + ghr);
                float zv = fsigmoid(gxz + ghz);
                float nv = ftanh(gxn + rv * ghn);
                float hn = (1.f - zv) * nv + zv * h[kk];
                h[kk] = hn;
                __nv_bfloat16 hv = __float2bfloat16(hn);
                hhi[nbuf * 1088 + hr * HB_S + j] = hv;
                hlo[nbuf * 1088 + hr * HB_S + j] = __float2bfloat16(hn - __bfloat162float(hv));
                float contrib = hn * ((kk & 2) ? wy1 : wy0);
                if (kk & 1) p1 += contrib; else p0 += contrib;
            }
            p0 += __shfl_down_sync(0xffffffffu, p0, 16);
            p1 += __shfl_down_sync(0xffffffffu, p1, 16);
            p0 += __shfl_down_sync(0xffffffffu, p0, 8);
            p1 += __shfl_down_sync(0xffffffffu, p1, 8);
            p0 += __shfl_down_sync(0xffffffffu, p0, 4);
            p1 += __shfl_down_sync(0xffffffffu, p1, 4);
            if (grp == 0) {
                part[buf * 64 + W * 8 + hr0] = p0;
                part[buf * 64 + W * 8 + hr1] = p1;
            }
        }

        // ---- stage eps(t+2) ----
        if (tid < 128) {
            int r = tid >> 4, k = tid & 15;
            __nv_bfloat16 pv = __float2bfloat16(epv);
            ehi[buf * 160 + r * 20 + k] = pv;
            elo[buf * 160 + r * 20 + k] = __float2bfloat16(epv - __bfloat162float(pv));
        }

        asm volatile("cp.async.wait_group 0;");
        __syncthreads();

        // ---- epilogue: logits(t) ----
        if (tid < 8 && tid < nr) {
            float s = 0.f;
            #pragma unroll
            for (int w = 0; w < 8; w++) s += part[buf * 64 + w * 8 + tid];
            float logit = s + by0;
            size_t o = ((size_t)(r0 + tid) * TT + t) * 2;
            out[o]     = logit;
            out[o + 1] = fsigmoid(logit);
        }
    }
}

// ============================================================================
extern "C" void kernel_launch(void* const* d_in, const int* in_sizes, int n_in,
                              void* d_out, int out_size) {
    const float* x   = (const float*)d_in[0];
    const int*   a   = (const int*)  d_in[1];
    const int*   t   = (const int*)  d_in[2];
    const float* y   = (const float*)d_in[3];
    const float* eps = (const float*)d_in[5];
    const float* Wx  = (const float*)d_in[6];
    const float* bx  = (const float*)d_in[7];
    const float* Ea  = (const float*)d_in[8];
    const float* Et  = (const float*)d_in[9];
    const float* Wih = (const float*)d_in[10];
    const float* Whh = (const float*)d_in[11];
    const float* bih = (const float*)d_in[12];
    const float* bhh = (const float*)d_in[13];
    const float* W0  = (const float*)d_in[14];
    const float* b0  = (const float*)d_in[15];
    const float* Wy  = (const float*)d_in[16];
    const float* by  = (const float*)d_in[17];
    float* out = (float*)d_out;

    cudaFuncSetAttribute(k_rnn, cudaFuncAttributeMaxDynamicSharedMemorySize, SMB);

    k_pro<<<1824, 384>>>(x, Wx, bx, eps, W0, b0, Ea, Et, Wih, bih, bhh);
    k_rnn<<<NB, 256, SMB>>>(a, t, y, eps, Wih, Whh, bhh, Wy, by, out);
}